// round 6
// baseline (speedup 1.0000x reference)
#include <cuda_runtime.h>
#include <math.h>

#define B_      8
#define C_      512
#define K_      19
#define HW_     16384
#define NCHUNK  64            // px chunks per image for pooling partials
#define PXT     256           // pixels per k1b block
#define XSPAD   516           // padded u64 row width for x px-pair slab

typedef unsigned long long u64;

__device__ __forceinline__ u64 ffma2(u64 a, u64 b, u64 c) {
    u64 d; asm("fma.rn.f32x2 %0, %1, %2, %3;" : "=l"(d) : "l"(a), "l"(b), "l"(c)); return d;
}
__device__ __forceinline__ u64 pack2(float lo, float hi) {
    u64 d; asm("mov.b64 %0, {%1, %2};" : "=l"(d) : "f"(lo), "f"(hi)); return d;
}
__device__ __forceinline__ float2 unpack2(u64 v) {
    float2 r; asm("mov.b64 {%0, %1}, %2;" : "=f"(r.x), "=f"(r.y) : "l"(v)); return r;
}

// Scratch (device globals — no allocation allowed)
__device__ float g_mask[B_ * K_ * HW_];               // ~10 MB
__device__ float g_partial[B_ * NCHUNK * K_ * C_];    // ~19.9 MB
__device__ float g_cf[B_ * K_ * C_];
__device__ float g_filters[B_ * K_ * C_];

// -------------------------------------------------------------------------
// k1a: mask[b,k,p] = sigmoid(sum_c Wm[k,c] x[b,c,p] + bm[k])
// 256 blocks (b x 32 segs of 512 px), 512 thr, 1 px/thread.
// acc[19] u64 (c-pair lanes) -> ~58 regs -> 32 warps/SM.
// 8 c-rows per iter, prefetched into regs before the FMA body.
// -------------------------------------------------------------------------
__global__ __launch_bounds__(512, 2)
void k1a_mask(const float* __restrict__ x,
              const float* __restrict__ Wm,
              const float* __restrict__ bm)
{
    __shared__ __align__(16) float Wm_s[K_ * C_];   // 38912 B
    __shared__ float bm_s[K_];

    const int t   = threadIdx.x;
    const int b   = blockIdx.x >> 5;
    const int seg = blockIdx.x & 31;
    const int p   = seg * 512 + t;

    for (int i = t; i < K_ * C_; i += 512) Wm_s[i] = Wm[i];
    if (t < K_) bm_s[t] = bm[t];

    const float* xp = x + (size_t)b * C_ * HW_ + p;

    u64 acc[K_];
    #pragma unroll
    for (int k = 0; k < K_; k++) acc[k] = 0ull;

    __syncthreads();

    float r[8];
    #pragma unroll
    for (int j = 0; j < 8; j++) r[j] = xp[(size_t)j * HW_];

    for (int c = 0; c < C_; c += 8) {
        const u64 a01 = pack2(r[0], r[1]);
        const u64 a23 = pack2(r[2], r[3]);
        const u64 a45 = pack2(r[4], r[5]);
        const u64 a67 = pack2(r[6], r[7]);

        if (c + 8 < C_) {
            #pragma unroll
            for (int j = 0; j < 8; j++) r[j] = xp[(size_t)(c + 8 + j) * HW_];
        }

        #pragma unroll
        for (int k = 0; k < K_; k++) {
            const ulonglong2 wA = *(const ulonglong2*)&Wm_s[k * C_ + c];
            const ulonglong2 wB = *(const ulonglong2*)&Wm_s[k * C_ + c + 4];
            acc[k] = ffma2(a01, wA.x, acc[k]);
            acc[k] = ffma2(a23, wA.y, acc[k]);
            acc[k] = ffma2(a45, wB.x, acc[k]);
            acc[k] = ffma2(a67, wB.y, acc[k]);
        }
    }

    float* mb = g_mask + (size_t)b * K_ * HW_ + p;
    #pragma unroll
    for (int k = 0; k < K_; k++) {
        const float2 f = unpack2(acc[k]);
        const float s = f.x + f.y + bm_s[k];
        mb[(size_t)k * HW_] = 1.0f / (1.0f + __expf(-s));
    }
}

// -------------------------------------------------------------------------
// k1b: partial[b,ch,k,c] = sum_{p in 256-px chunk} mask[b,k,p] * x[b,c,p]
// 512 blocks (b x 64 chunks), 512 thr (thread = single c).
// FFMA2 lanes = px-pairs. mask staged as u64 px-pairs (warp-uniform LDS.128
// covering 2 pairs per k). x staged per 8-px slab as u64 px-pairs, LDS.64
// conflict-free. acc[19] u64 -> high occupancy.
// -------------------------------------------------------------------------
__global__ __launch_bounds__(512, 2)
void k1b_pool(const float* __restrict__ x)
{
    __shared__ __align__(16) u64 mask2_s[K_][128];    // 19456 B (px-pairs)
    __shared__ __align__(16) u64 x2_s[4][XSPAD];      // 16512 B (px-pairs for 8 px)

    const int t     = threadIdx.x;
    const int b     = blockIdx.x >> 6;
    const int ch    = blockIdx.x & 63;
    const int pbase = ch * PXT;
    const int c     = t;

    // stage mask px-pairs (coalesced 8B loads)
    {
        const u64* mb = (const u64*)(g_mask + (size_t)b * K_ * HW_ + pbase);
        for (int i = t; i < K_ * 128; i += 512) {
            const int k  = i >> 7;
            const int pr = i & 127;
            mask2_s[k][pr] = mb[(size_t)k * (HW_ / 2) + pr];
        }
    }

    const float* xb = x + (size_t)b * C_ * HW_;

    u64 acc[K_];
    #pragma unroll
    for (int k = 0; k < K_; k++) acc[k] = 0ull;

    __syncthreads();

    for (int pp0 = 0; pp0 < PXT; pp0 += 8) {
        // ---- stage x slab: 512 c x 8 px as px-pair u64s ----
        #pragma unroll
        for (int it = 0; it < 2; it++) {
            const int idx = it * 512 + t;         // (c, q) with q inner
            const int cc  = idx >> 1;
            const int q   = idx & 1;
            const float4 v = *(const float4*)&xb[(size_t)cc * HW_ + pbase + pp0 + q * 4];
            x2_s[q * 2 + 0][cc] = pack2(v.x, v.y);
            x2_s[q * 2 + 1][cc] = pack2(v.z, v.w);
        }
        __syncthreads();

        // ---- compute: two px-pairs per step (mask via LDS.128) ----
        const int colb = pp0 >> 1;
        #pragma unroll
        for (int pw = 0; pw < 4; pw += 2) {
            const u64 xv0 = x2_s[pw + 0][c];
            const u64 xv1 = x2_s[pw + 1][c];
            #pragma unroll
            for (int k = 0; k < K_; k++) {
                const ulonglong2 m = *(const ulonglong2*)&mask2_s[k][colb + pw];  // broadcast
                acc[k] = ffma2(xv0, m.x, acc[k]);
                acc[k] = ffma2(xv1, m.y, acc[k]);
            }
        }
        __syncthreads();   // protect x2_s before next stage
    }

    float* dst = g_partial + (size_t)(b * NCHUNK + ch) * K_ * C_;
    #pragma unroll
    for (int k = 0; k < K_; k++) {
        const float2 f = unpack2(acc[k]);
        dst[k * C_ + c] = f.x + f.y;
    }
}

// -------------------------------------------------------------------------
// k2: deterministic reduction of partials -> class_feat / (h*w)
// -------------------------------------------------------------------------
__global__ __launch_bounds__(512)
void k2_reduce()
{
    const int bk = blockIdx.x;
    const int c  = threadIdx.x;
    const int b  = bk / K_;
    const int k  = bk % K_;

    const float* src = g_partial + ((size_t)b * NCHUNK * K_ + k) * C_ + c;
    float s = 0.f;
    #pragma unroll 8
    for (int ch = 0; ch < NCHUNK; ch++)
        s += src[(size_t)ch * K_ * C_];
    g_cf[(b * K_ + k) * C_ + c] = s * (1.0f / (float)HW_);
}

// -------------------------------------------------------------------------
// k3: filters[b,k,o] = sum_c Wf[k,o,c] * cf[b,k,c] + bf[k,o]
// Grid (19, 64), 256 thr = 8 warps; warp owns one o, lane owns c-chunk.
// Wf reads: warp-contiguous 512B LDG.128 (coalesced). cf b-major in smem,
// 16B lane stride (conflict-free LDS.128). Deterministic butterfly reduce.
// -------------------------------------------------------------------------
__global__ __launch_bounds__(256)
void k3_filters(const float* __restrict__ Wf, const float* __restrict__ bf)
{
    __shared__ __align__(16) float cf_s[B_][XSPAD];   // b-major, 16512 B

    const int k    = blockIdx.x;
    const int og   = blockIdx.y;
    const int t    = threadIdx.x;
    const int w    = t >> 5;
    const int lane = t & 31;
    const int o    = og * 8 + w;

    for (int i = t; i < B_ * C_; i += 256) {
        const int bb = i >> 9;
        const int cc = i & 511;
        cf_s[bb][cc] = g_cf[(bb * K_ + k) * C_ + cc];
    }
    __syncthreads();

    const float* wrow = Wf + ((size_t)k * C_ + o) * C_;

    float acc[B_];
    #pragma unroll
    for (int bb = 0; bb < B_; bb++) acc[bb] = 0.f;

    #pragma unroll
    for (int ccq = 0; ccq < 4; ccq++) {
        const int cbase = ccq * 128 + lane * 4;
        const float4 wv = *(const float4*)(wrow + cbase);
        #pragma unroll
        for (int bb = 0; bb < B_; bb++) {
            const float4 f = *(const float4*)&cf_s[bb][cbase];
            acc[bb] = fmaf(wv.x, f.x,
                      fmaf(wv.y, f.y,
                      fmaf(wv.z, f.z,
                      fmaf(wv.w, f.w, acc[bb]))));
        }
    }

    // deterministic butterfly reduce over lanes
    #pragma unroll
    for (int off = 16; off >= 1; off >>= 1) {
        #pragma unroll
        for (int bb = 0; bb < B_; bb++)
            acc[bb] += __shfl_xor_sync(0xffffffffu, acc[bb], off);
    }

    if (lane < B_)
        g_filters[((size_t)lane * K_ + k) * C_ + o] = acc[lane] + bf[k * C_ + o];
}

// -------------------------------------------------------------------------
// k4: pred[b,k,p] = sum_c filters[b,k,c] * x[b,c,p]
// Same structure as k1a: 512 thr, 1 px/thread, acc[19] u64.
// -------------------------------------------------------------------------
__global__ __launch_bounds__(512, 2)
void k4_pred(const float* __restrict__ x, float* __restrict__ out)
{
    __shared__ __align__(16) float f_s[K_ * C_];   // 38912 B

    const int t   = threadIdx.x;
    const int b   = blockIdx.x >> 5;
    const int seg = blockIdx.x & 31;
    const int p   = seg * 512 + t;

    for (int i = t; i < K_ * C_; i += 512)
        f_s[i] = g_filters[(size_t)b * K_ * C_ + i];

    const float* xp = x + (size_t)b * C_ * HW_ + p;

    u64 acc[K_];
    #pragma unroll
    for (int k = 0; k < K_; k++) acc[k] = 0ull;

    __syncthreads();

    float r[8];
    #pragma unroll
    for (int j = 0; j < 8; j++) r[j] = xp[(size_t)j * HW_];

    for (int c = 0; c < C_; c += 8) {
        const u64 a01 = pack2(r[0], r[1]);
        const u64 a23 = pack2(r[2], r[3]);
        const u64 a45 = pack2(r[4], r[5]);
        const u64 a67 = pack2(r[6], r[7]);

        if (c + 8 < C_) {
            #pragma unroll
            for (int j = 0; j < 8; j++) r[j] = xp[(size_t)(c + 8 + j) * HW_];
        }

        #pragma unroll
        for (int k = 0; k < K_; k++) {
            const ulonglong2 wA = *(const ulonglong2*)&f_s[k * C_ + c];
            const ulonglong2 wB = *(const ulonglong2*)&f_s[k * C_ + c + 4];
            acc[k] = ffma2(a01, wA.x, acc[k]);
            acc[k] = ffma2(a23, wA.y, acc[k]);
            acc[k] = ffma2(a45, wB.x, acc[k]);
            acc[k] = ffma2(a67, wB.y, acc[k]);
        }
    }

    float* ob = out + (size_t)b * K_ * HW_ + p;
    #pragma unroll
    for (int k = 0; k < K_; k++) {
        const float2 f = unpack2(acc[k]);
        ob[(size_t)k * HW_] = f.x + f.y;
    }
}

// -------------------------------------------------------------------------
extern "C" void kernel_launch(void* const* d_in, const int* in_sizes, int n_in,
                              void* d_out, int out_size)
{
    const float* x  = (const float*)d_in[0];
    const float* Wm = (const float*)d_in[1];
    const float* bm = (const float*)d_in[2];
    const float* Wf = (const float*)d_in[3];
    const float* bf = (const float*)d_in[4];
    float* out = (float*)d_out;

    k1a_mask  <<<B_ * 32, 512>>>(x, Wm, bm);
    k1b_pool  <<<B_ * NCHUNK, 512>>>(x);
    k2_reduce <<<B_ * K_, 512>>>();
    k3_filters<<<dim3(K_, 64), 256>>>(Wf, bf);
    k4_pred   <<<B_ * 32, 512>>>(x, out);
}